// round 10
// baseline (speedup 1.0000x reference)
#include <cuda_runtime.h>
#include <cuda_bf16.h>
#include <cstdint>

// Problem constants (from reference)
#define Bq 128
#define Nq 36
#define Dq 512
#define D4q 128          // Dq/4
#define Gq 2
#define NDq (Nq * Dq)
#define NEGV -1e10f
#define PST 132          // padded row stride (floats) for logit partials

// Dynamic smem layout (bytes, 16B aligned)
#define OFF_OBJ    0                   // float4[36*128]   = 73728
#define OFF_SWP    73728               // float4[4][256]   = 16384
#define OFF_TP     90112               // float4[4][256]   = 16384
#define OFF_SWF    106496              // float4[256]      = 4096
#define OFF_TF     110592              // float4[256]      = 4096
#define OFF_PART   114688              // float[72*132]    = 38016
#define OFF_LOGIT  152704              // float[72]        = 288
#define OFF_WEIGHT 152992              // float[72]        = 288
#define OFF_MROW   153280              // int[36]          = 144
#define OFF_BIAS   153424              // float[2]         = 8
#define OFF_FLAG   153432              // int              = 4
#define SMEM_TOTAL 153440

// One block per batch element, 1024 threads, single wave (128 CTAs).
// One global burst, then smem-only; 5 barriers total.
// logits factorization:
//   logit[b,n,g] = sum_d o[n,d]^2*SW[g,d] - o[n,d]*T[b,g,d]
//   SW[g,d] = sum_m W[g,m,d], T[b,g,d] = sum_m W[g,m,d]*o[b,m,d]
__global__ __launch_bounds__(1024, 1)
void qgen_attn_kernel(const float* __restrict__ obj,   // [B, N, D]
                      const float* __restrict__ W,     // [G, N*D]
                      const float* __restrict__ bias,  // [G]
                      const unsigned char* __restrict__ mask_bytes, // [B,N]
                      float* __restrict__ out)         // [B, G*D]
{
    extern __shared__ __align__(16) char dsm[];
    float4* obj_s4   = (float4*)(dsm + OFF_OBJ);
    float4* swp      = (float4*)(dsm + OFF_SWP);
    float4* tp       = (float4*)(dsm + OFF_TP);
    float4* SWf      = (float4*)(dsm + OFF_SWF);   // [g*128 + d4]
    float4* Tf       = (float4*)(dsm + OFF_TF);
    float*  part     = (float*)(dsm + OFF_PART);   // [(n*2+g)*PST + d4]
    float*  logit_s  = (float*)(dsm + OFF_LOGIT);
    float*  weight_s = (float*)(dsm + OFF_WEIGHT);
    int*    mrow_s   = (int*)(dsm + OFF_MROW);
    float*  bias_s   = (float*)(dsm + OFF_BIAS);
    int*    flag     = (int*)(dsm + OFF_FLAG);

    const int b   = blockIdx.x;
    const int tid = threadIdx.x;      // 0..1023
    const int warp = tid >> 5, lane = tid & 31;

    // ---- Mask dtype detection: warp 18, before phase 1, no barrier needed ----
    // int32 mask => every byte at offset%4!=0 (bits 8..31 of each LE word) is 0.
    // 256 bytes are in-bounds for both interpretations. Ballot -> flag STS.
    if (warp == 18) {
        const uint32_t* mw = (const uint32_t*)mask_bytes;
        uint32_t w0 = __ldg(mw + 2 * lane);
        uint32_t w1 = __ldg(mw + 2 * lane + 1);
        const bool vote = ((w0 | w1) & 0xFFFFFF00u) != 0u;
        const uint32_t bal = __ballot_sync(0xffffffffu, vote);
        if (lane == 0) *flag = (bal != 0u) ? 1 : 0;
    }

    // bias prefetch: hold in reg, commit before the softmax barrier.
    float bias_v = 0.f;
    const bool is_biaspref = (tid >= 612 && tid < 614);
    if (is_biaspref) bias_v = __ldg(bias + (tid - 612));

    // ---- Phase 1: the only global burst. obj+W LDG, obj -> smem, SW/T partials ----
    const int col = tid & 255;         // (g1,d4)
    const int g1  = col >> 7;
    const int d4  = col & 127;
    const int ms  = tid >> 8;          // 0..3, 9 m's each
    const float4* __restrict__ W4    = (const float4*)(W + (size_t)g1 * NDq);
    const float4* __restrict__ obj4g = (const float4*)(obj + (size_t)b * NDq);

    {
        float4 sw = make_float4(0,0,0,0), t = make_float4(0,0,0,0);
        #pragma unroll
        for (int j = 0; j < 9; j++) {
            const int m = ms * 9 + j;
            float4 w = __ldg(W4    + m * D4q + d4);
            float4 o = __ldg(obj4g + m * D4q + d4);
            if (g1 == 0) obj_s4[m * D4q + d4] = o;
            sw.x += w.x; sw.y += w.y; sw.z += w.z; sw.w += w.w;
            t.x = fmaf(w.x, o.x, t.x);
            t.y = fmaf(w.y, o.y, t.y);
            t.z = fmaf(w.z, o.z, t.z);
            t.w = fmaf(w.w, o.w, t.w);
        }
        swp[ms * 256 + col] = sw;
        tp [ms * 256 + col] = t;
    }
    __syncthreads();                                  // BAR1 (obj_s, partials, flag)

    // mask-row prefetch (flag is final; LDG latency hidden behind phases 2/3)
    int mrow_v = 0;
    const bool is_maskpref = (tid >= 576 && tid < 576 + Nq);
    if (is_maskpref) {
        const int i = tid - 576;
        if (*flag == 0) mrow_v = __ldg((const int*)mask_bytes + b * Nq + i);
        else            mrow_v = (int)__ldg(mask_bytes + b * Nq + i);
    }

    // ---- Phase 2: reduce 4 slices -> SW/T final ----
    if (tid < 256) {
        float4 s0 = swp[tid], s1 = swp[256+tid], s2 = swp[512+tid], s3 = swp[768+tid];
        float4 t0 = tp[tid],  t1 = tp[256+tid],  t2 = tp[512+tid],  t3 = tp[768+tid];
        SWf[tid] = make_float4(s0.x+s1.x+s2.x+s3.x, s0.y+s1.y+s2.y+s3.y,
                               s0.z+s1.z+s2.z+s3.z, s0.w+s1.w+s2.w+s3.w);
        Tf[tid]  = make_float4(t0.x+t1.x+t2.x+t3.x, t0.y+t1.y+t2.y+t3.y,
                               t0.z+t1.z+t2.z+t3.z, t0.w+t1.w+t2.w+t3.w);
    }
    __syncthreads();                                  // BAR2

    // ---- Phase 3A: logit partials. 128 d4-cols x 8 n-slices ----
    {
        const int d4c = tid & 127;
        const int nsl = tid >> 7;     // 0..7
        const float4 sw0 = SWf[d4c],        sw1 = SWf[128 + d4c];
        const float4 t0  = Tf[d4c],         t1  = Tf[128 + d4c];
        for (int n = nsl; n < Nq; n += 8) {
            float4 o = obj_s4[n * D4q + d4c];
            float p0 = fmaf(o.x, fmaf(o.x, sw0.x, -t0.x), 0.f);
            p0 = fmaf(o.y, fmaf(o.y, sw0.y, -t0.y), p0);
            p0 = fmaf(o.z, fmaf(o.z, sw0.z, -t0.z), p0);
            p0 = fmaf(o.w, fmaf(o.w, sw0.w, -t0.w), p0);
            float p1 = fmaf(o.x, fmaf(o.x, sw1.x, -t1.x), 0.f);
            p1 = fmaf(o.y, fmaf(o.y, sw1.y, -t1.y), p1);
            p1 = fmaf(o.z, fmaf(o.z, sw1.z, -t1.z), p1);
            p1 = fmaf(o.w, fmaf(o.w, sw1.w, -t1.w), p1);
            part[(n * 2 + 0) * PST + d4c] = p0;
            part[(n * 2 + 1) * PST + d4c] = p1;
        }
    }
    __syncthreads();                                  // BAR3a

    // ---- Phase 3B: reduce 128 partials per (n,g). 72 8-lane groups ----
    {
        const int gid = tid >> 3;     // 0..127
        const int l   = tid & 7;
        if (gid < Nq * Gq) {
            const float4* pr = (const float4*)(part + gid * PST);
            float acc = 0.f;
            #pragma unroll
            for (int k = 0; k < 4; k++) {
                float4 v = pr[l + 8 * k];
                acc += v.x + v.y + v.z + v.w;
            }
            acc += __shfl_xor_sync(0xffffffffu, acc, 4, 8);
            acc += __shfl_xor_sync(0xffffffffu, acc, 2, 8);
            acc += __shfl_xor_sync(0xffffffffu, acc, 1, 8);
            if (l == 0) logit_s[gid] = acc;
        }
    }
    // commit prefetches
    if (is_maskpref) mrow_s[tid - 576] = mrow_v;
    if (is_biaspref) bias_s[tid - 612] = bias_v;
    __syncthreads();                                  // BAR3b

    // ---- Phase 4: masked softmax over n; warp 0 -> g=0, warp 16 -> g=1 ----
    if ((warp & 15) == 0) {
        const int g  = warp >> 4;
        const int n0 = lane, n1 = lane + 32;
        float x0 = mrow_s[n0] ? (logit_s[n0 * Gq + g] + bias_s[g]) : NEGV;
        float x1 = -1e30f;
        if (n1 < Nq) x1 = mrow_s[n1] ? (logit_s[n1 * Gq + g] + bias_s[g]) : NEGV;
        float mx = fmaxf(x0, x1);
        #pragma unroll
        for (int off = 16; off > 0; off >>= 1)
            mx = fmaxf(mx, __shfl_xor_sync(0xffffffffu, mx, off));
        float e0 = __expf(x0 - mx);
        float e1 = (n1 < Nq) ? __expf(x1 - mx) : 0.f;
        float s = e0 + e1;
        #pragma unroll
        for (int off = 16; off > 0; off >>= 1)
            s += __shfl_xor_sync(0xffffffffu, s, off);
        const float inv = 1.f / s;
        weight_s[n0 * Gq + g] = e0 * inv;
        if (n1 < Nq) weight_s[n1 * Gq + g] = e1 * inv;
    }
    __syncthreads();                                  // BAR4

    // ---- Phase 5: output, shuffle-fused. 256 outputs x 4 adjacent-lane slices ----
    {
        const int nsl = tid & 3;          // n-slice on adjacent lanes
        const int grp = tid >> 2;         // 0..255
        const int g   = grp >> 7;
        const int d4o = grp & 127;
        float4 acc = make_float4(0,0,0,0);
        #pragma unroll
        for (int k = 0; k < 9; k++) {
            const int n = nsl + 4 * k;    // covers 0..35 exactly
            const float wn = weight_s[n * Gq + g];
            float4 o = obj_s4[n * D4q + d4o];   // broadcast across the 4 lanes
            acc.x = fmaf(wn, o.x, acc.x);
            acc.y = fmaf(wn, o.y, acc.y);
            acc.z = fmaf(wn, o.z, acc.z);
            acc.w = fmaf(wn, o.w, acc.w);
        }
        #pragma unroll
        for (int off = 1; off < 4; off <<= 1) {
            acc.x += __shfl_xor_sync(0xffffffffu, acc.x, off);
            acc.y += __shfl_xor_sync(0xffffffffu, acc.y, off);
            acc.z += __shfl_xor_sync(0xffffffffu, acc.z, off);
            acc.w += __shfl_xor_sync(0xffffffffu, acc.w, off);
        }
        if (nsl == 0)
            ((float4*)(out + (size_t)b * (Gq * Dq)))[g * D4q + d4o] = acc;
    }
}

extern "C" void kernel_launch(void* const* d_in, const int* in_sizes, int n_in,
                              void* d_out, int out_size) {
    const float*         obj  = (const float*)d_in[0];         // [128, 36, 512]
    const float*         W    = (const float*)d_in[1];         // [2, 36*512]
    const float*         bias = (const float*)d_in[2];         // [2]
    const unsigned char* mask = (const unsigned char*)d_in[3]; // [128, 36]
    float* out = (float*)d_out;                                // [128, 1024]

    cudaFuncSetAttribute(qgen_attn_kernel,
                         cudaFuncAttributeMaxDynamicSharedMemorySize, SMEM_TOTAL);
    qgen_attn_kernel<<<Bq, 1024, SMEM_TOTAL>>>(obj, W, bias, mask, out);
}

// round 11
// speedup vs baseline: 1.2113x; 1.2113x over previous
#include <cuda_runtime.h>
#include <cuda_bf16.h>
#include <cstdint>

// Problem constants (from reference)
#define Bq 128
#define Nq 36
#define Dq 512
#define D4q 128          // Dq/4
#define Gq 2
#define NDq (Nq * Dq)
#define NEGV -1e10f
#define PST 132          // padded row stride (floats) for logit partials

// Dynamic smem layout (bytes, 16B aligned)
#define OFF_OBJ    0                   // float4[36*128]     = 73728
#define OFF_SWP    73728               // float4[8][2][128]  = 32768
#define OFF_TP     106496              // float4[8][2][128]  = 32768
#define OFF_SWF    139264              // float4[256]        = 4096
#define OFF_TF     143360              // float4[256]        = 4096
#define OFF_PART   147456              // float[72*132]      = 38016
#define OFF_LOGIT  185472              // float[72]          = 288
#define OFF_WEIGHT 185760              // float[72]          = 288
#define OFF_MROW   186048              // int[36]            = 144
#define OFF_BIAS   186192              // float[2]           = 8
#define OFF_FLAG   186200              // int                = 4
#define SMEM_TOTAL 186208

// One block per batch element, 1024 threads, single wave (128 CTAs).
// One global burst (obj fetched exactly ONCE per CTA), then smem-only.
// logits factorization:
//   logit[b,n,g] = sum_d o[n,d]^2*SW[g,d] - o[n,d]*T[b,g,d]
//   SW[g,d] = sum_m W[g,m,d], T[b,g,d] = sum_m W[g,m,d]*o[b,m,d]
__global__ __launch_bounds__(1024, 1)
void qgen_attn_kernel(const float* __restrict__ obj,   // [B, N, D]
                      const float* __restrict__ W,     // [G, N*D]
                      const float* __restrict__ bias,  // [G]
                      const unsigned char* __restrict__ mask_bytes, // [B,N]
                      float* __restrict__ out)         // [B, G*D]
{
    extern __shared__ __align__(16) char dsm[];
    float4* obj_s4   = (float4*)(dsm + OFF_OBJ);
    float4* swp      = (float4*)(dsm + OFF_SWP);   // [(sl*2+g)*128 + d4]
    float4* tp       = (float4*)(dsm + OFF_TP);
    float4* SWf      = (float4*)(dsm + OFF_SWF);   // [g*128 + d4]
    float4* Tf       = (float4*)(dsm + OFF_TF);
    float*  part     = (float*)(dsm + OFF_PART);   // [(n*2+g)*PST + d4]
    float*  logit_s  = (float*)(dsm + OFF_LOGIT);
    float*  weight_s = (float*)(dsm + OFF_WEIGHT);
    int*    mrow_s   = (int*)(dsm + OFF_MROW);
    float*  bias_s   = (float*)(dsm + OFF_BIAS);
    volatile int* flag = (int*)(dsm + OFF_FLAG);

    const int b   = blockIdx.x;
    const int tid = threadIdx.x;      // 0..1023
    const int warp = tid >> 5, lane = tid & 31;

    if (tid == 0) *flag = 0;
    __syncthreads();                                  // BAR0

    // mask dtype detection: bytes at offset%4!=0 all zero iff int32 (in-bounds
    // for both interpretations). Plain stores: race writes same value.
    if (tid < 256 && (tid & 3) != 0) {
        if (mask_bytes[tid] != 0) *flag = 1;
    }

    // bias prefetch: hold in reg, commit before the softmax barrier.
    float bias_v = 0.f;
    const bool is_biaspref = (tid >= 612 && tid < 614);
    if (is_biaspref) bias_v = __ldg(bias + (tid - 612));

    // ---- Phase 1: the only global burst. obj loaded ONCE; both g's per thread ----
    const int d4 = tid & 127;          // float4 column
    const int sl = tid >> 7;           // 0..7 m-slice (4-5 m's each)
    const float4* __restrict__ W40   = (const float4*)W;
    const float4* __restrict__ W41   = (const float4*)(W + NDq);
    const float4* __restrict__ obj4g = (const float4*)(obj + (size_t)b * NDq);

    {
        float4 sw0 = make_float4(0,0,0,0), sw1 = make_float4(0,0,0,0);
        float4 t0  = make_float4(0,0,0,0), t1  = make_float4(0,0,0,0);
        for (int m = sl; m < Nq; m += 8) {
            float4 o  = __ldg(obj4g + m * D4q + d4);
            float4 w0 = __ldg(W40   + m * D4q + d4);
            float4 w1 = __ldg(W41   + m * D4q + d4);
            obj_s4[m * D4q + d4] = o;
            sw0.x += w0.x; sw0.y += w0.y; sw0.z += w0.z; sw0.w += w0.w;
            sw1.x += w1.x; sw1.y += w1.y; sw1.z += w1.z; sw1.w += w1.w;
            t0.x = fmaf(w0.x, o.x, t0.x); t0.y = fmaf(w0.y, o.y, t0.y);
            t0.z = fmaf(w0.z, o.z, t0.z); t0.w = fmaf(w0.w, o.w, t0.w);
            t1.x = fmaf(w1.x, o.x, t1.x); t1.y = fmaf(w1.y, o.y, t1.y);
            t1.z = fmaf(w1.z, o.z, t1.z); t1.w = fmaf(w1.w, o.w, t1.w);
        }
        swp[(sl * 2 + 0) * D4q + d4] = sw0;
        swp[(sl * 2 + 1) * D4q + d4] = sw1;
        tp [(sl * 2 + 0) * D4q + d4] = t0;
        tp [(sl * 2 + 1) * D4q + d4] = t1;
    }
    __syncthreads();                                  // BAR1 (obj_s, partials, flag)

    // mask-row prefetch (flag final; LDG latency hidden behind phases 2/3)
    int mrow_v = 0;
    const bool is_maskpref = (tid >= 576 && tid < 576 + Nq);
    if (is_maskpref) {
        const int i = tid - 576;
        if (*flag == 0) mrow_v = __ldg((const int*)mask_bytes + b * Nq + i);
        else            mrow_v = (int)__ldg(mask_bytes + b * Nq + i);
    }

    // ---- Phase 2: reduce 8 slices -> SW/T final (256 threads: g,d4) ----
    if (tid < 256) {
        const int g   = tid >> 7;
        const int d4r = tid & 127;
        float4 sa = make_float4(0,0,0,0), ta = make_float4(0,0,0,0);
        #pragma unroll
        for (int s = 0; s < 8; s++) {
            float4 sv = swp[(s * 2 + g) * D4q + d4r];
            float4 tv = tp [(s * 2 + g) * D4q + d4r];
            sa.x += sv.x; sa.y += sv.y; sa.z += sv.z; sa.w += sv.w;
            ta.x += tv.x; ta.y += tv.y; ta.z += tv.z; ta.w += tv.w;
        }
        SWf[tid] = sa;
        Tf[tid]  = ta;
    }
    __syncthreads();                                  // BAR2

    // ---- Phase 3A: logit partials. 128 d4-cols x 8 n-slices ----
    {
        const int d4c = tid & 127;
        const int nsl = tid >> 7;     // 0..7
        const float4 sw0 = SWf[d4c],        sw1 = SWf[128 + d4c];
        const float4 t0  = Tf[d4c],         t1  = Tf[128 + d4c];
        for (int n = nsl; n < Nq; n += 8) {
            float4 o = obj_s4[n * D4q + d4c];
            float p0 = fmaf(o.x, fmaf(o.x, sw0.x, -t0.x), 0.f);
            p0 = fmaf(o.y, fmaf(o.y, sw0.y, -t0.y), p0);
            p0 = fmaf(o.z, fmaf(o.z, sw0.z, -t0.z), p0);
            p0 = fmaf(o.w, fmaf(o.w, sw0.w, -t0.w), p0);
            float p1 = fmaf(o.x, fmaf(o.x, sw1.x, -t1.x), 0.f);
            p1 = fmaf(o.y, fmaf(o.y, sw1.y, -t1.y), p1);
            p1 = fmaf(o.z, fmaf(o.z, sw1.z, -t1.z), p1);
            p1 = fmaf(o.w, fmaf(o.w, sw1.w, -t1.w), p1);
            part[(n * 2 + 0) * PST + d4c] = p0;
            part[(n * 2 + 1) * PST + d4c] = p1;
        }
    }
    __syncthreads();                                  // BAR3a

    // ---- Phase 3B: reduce 128 partials per (n,g). 72 8-lane groups ----
    {
        const int gid = tid >> 3;     // 0..127
        const int l   = tid & 7;
        if (gid < Nq * Gq) {
            const float4* pr = (const float4*)(part + gid * PST);
            float acc = 0.f;
            #pragma unroll
            for (int k = 0; k < 4; k++) {
                float4 v = pr[l + 8 * k];
                acc += v.x + v.y + v.z + v.w;
            }
            acc += __shfl_xor_sync(0xffffffffu, acc, 4, 8);
            acc += __shfl_xor_sync(0xffffffffu, acc, 2, 8);
            acc += __shfl_xor_sync(0xffffffffu, acc, 1, 8);
            if (l == 0) logit_s[gid] = acc;
        }
    }
    // commit prefetches
    if (is_maskpref) mrow_s[tid - 576] = mrow_v;
    if (is_biaspref) bias_s[tid - 612] = bias_v;
    __syncthreads();                                  // BAR3b

    // ---- Phase 4: masked softmax over n; warp 0 -> g=0, warp 16 -> g=1 ----
    if ((warp & 15) == 0) {
        const int g  = warp >> 4;
        const int n0 = lane, n1 = lane + 32;
        float x0 = mrow_s[n0] ? (logit_s[n0 * Gq + g] + bias_s[g]) : NEGV;
        float x1 = -1e30f;
        if (n1 < Nq) x1 = mrow_s[n1] ? (logit_s[n1 * Gq + g] + bias_s[g]) : NEGV;
        float mx = fmaxf(x0, x1);
        #pragma unroll
        for (int off = 16; off > 0; off >>= 1)
            mx = fmaxf(mx, __shfl_xor_sync(0xffffffffu, mx, off));
        float e0 = __expf(x0 - mx);
        float e1 = (n1 < Nq) ? __expf(x1 - mx) : 0.f;
        float s = e0 + e1;
        #pragma unroll
        for (int off = 16; off > 0; off >>= 1)
            s += __shfl_xor_sync(0xffffffffu, s, off);
        const float inv = 1.f / s;
        weight_s[n0 * Gq + g] = e0 * inv;
        if (n1 < Nq) weight_s[n1 * Gq + g] = e1 * inv;
    }
    __syncthreads();                                  // BAR4

    // ---- Phase 5A: output partials. 1024 threads = 2g x 4 n-slices x 128 d4 ----
    {
        const int g   = tid >> 9;
        const int nsl = (tid >> 7) & 3;
        const int d4o = tid & 127;
        float4 acc = make_float4(0,0,0,0);
        for (int n = nsl; n < Nq; n += 4) {
            const float wn = weight_s[n * Gq + g];
            float4 o = obj_s4[n * D4q + d4o];
            acc.x = fmaf(wn, o.x, acc.x);
            acc.y = fmaf(wn, o.y, acc.y);
            acc.z = fmaf(wn, o.z, acc.z);
            acc.w = fmaf(wn, o.w, acc.w);
        }
        swp[(g * 4 + nsl) * 128 + d4o] = acc;   // swp reused as out partials
    }
    __syncthreads();                                  // BAR5

    // ---- Phase 5B: reduce 4 slices, one STG.128 per thread ----
    if (tid < 256) {
        const int g   = tid >> 7;
        const int d4o = tid & 127;
        float4 a0 = swp[(g*4+0)*128 + d4o];
        float4 a1 = swp[(g*4+1)*128 + d4o];
        float4 a2 = swp[(g*4+2)*128 + d4o];
        float4 a3 = swp[(g*4+3)*128 + d4o];
        float4 r = make_float4(a0.x+a1.x+a2.x+a3.x, a0.y+a1.y+a2.y+a3.y,
                               a0.z+a1.z+a2.z+a3.z, a0.w+a1.w+a2.w+a3.w);
        ((float4*)(out + (size_t)b * (Gq * Dq)))[g * D4q + d4o] = r;
    }
}

extern "C" void kernel_launch(void* const* d_in, const int* in_sizes, int n_in,
                              void* d_out, int out_size) {
    const float*         obj  = (const float*)d_in[0];         // [128, 36, 512]
    const float*         W    = (const float*)d_in[1];         // [2, 36*512]
    const float*         bias = (const float*)d_in[2];         // [2]
    const unsigned char* mask = (const unsigned char*)d_in[3]; // [128, 36]
    float* out = (float*)d_out;                                // [128, 1024]

    cudaFuncSetAttribute(qgen_attn_kernel,
                         cudaFuncAttributeMaxDynamicSharedMemorySize, SMEM_TOTAL);
    qgen_attn_kernel<<<Bq, 1024, SMEM_TOTAL>>>(obj, W, bias, mask, out);
}